// round 1
// baseline (speedup 1.0000x reference)
#include <cuda_runtime.h>
#include <math.h>

#define BB 64
#define CC 2048
#define CI 1024
#define NN 512   // H*W = 32*16

// ---------------- scratch (static device globals; no runtime allocs) ----------
__device__ float g_g [(size_t)BB * CI * NN];
__device__ float g_th[(size_t)BB * CI * NN];
__device__ float g_ph[(size_t)BB * CI * NN];
__device__ float g_f [(size_t)BB * NN * NN];
__device__ float g_y [(size_t)BB * CI * NN];
__device__ float g_mean[CC];
__device__ float g_rstd[CC];

// ---------------- generic batched SGEMM: C[m][n] = sum_k opA * opB (+bias[m]) --
// TA=false: A is [M x K] row-major (lda = row stride)
// TA=true : A is [K x M] row-major (lda = row stride) -> C += A[k][m]*...
// TB=false: B is [K x N] row-major (ldb)
// TB=true : B is [N x K] row-major (ldb) -> uses B[n][k]
// C is [M x N] row-major, contiguous per batch.
// Requires M%128==0, N%128==0, K%8==0.
template<bool TA, bool TB>
__global__ void __launch_bounds__(256)
sgemm_kernel(const float* __restrict__ A, const float* __restrict__ B,
             float* __restrict__ C, const float* __restrict__ bias,
             int M, int N, int K, int lda, int ldb,
             long bsA, long bsB, long bsC)
{
    const int b = blockIdx.z;
    A += (long)b * bsA;
    B += (long)b * bsB;
    C += (long)b * bsC;

    const int m0 = blockIdx.y * 128;
    const int n0 = blockIdx.x * 128;
    const int tid = threadIdx.x;
    const int tx = tid & 15;      // 16 cols of threads
    const int ty = tid >> 4;      // 16 rows of threads

    __shared__ float As[8][128];
    __shared__ float Bs[8][128];

    float acc[8][8];
#pragma unroll
    for (int i = 0; i < 8; ++i)
#pragma unroll
        for (int j = 0; j < 8; ++j) acc[i][j] = 0.f;

    for (int k0 = 0; k0 < K; k0 += 8) {
        // ---- load A tile into As[k][m]
        if (!TA) {
            const int row = tid >> 1;            // 0..127
            const int kc  = (tid & 1) * 4;       // 0 or 4
            float4 v = *reinterpret_cast<const float4*>(&A[(long)(m0 + row) * lda + k0 + kc]);
            As[kc + 0][row] = v.x;
            As[kc + 1][row] = v.y;
            As[kc + 2][row] = v.z;
            As[kc + 3][row] = v.w;
        } else {
            const int kr = tid >> 5;             // 0..7
            const int mc = (tid & 31) * 4;       // 0..124
            float4 v = *reinterpret_cast<const float4*>(&A[(long)(k0 + kr) * lda + m0 + mc]);
            *reinterpret_cast<float4*>(&As[kr][mc]) = v;
        }
        // ---- load B tile into Bs[k][n]
        if (!TB) {
            const int kr = tid >> 5;
            const int nc = (tid & 31) * 4;
            float4 v = *reinterpret_cast<const float4*>(&B[(long)(k0 + kr) * ldb + n0 + nc]);
            *reinterpret_cast<float4*>(&Bs[kr][nc]) = v;
        } else {
            const int nr = tid >> 1;             // 0..127
            const int kc = (tid & 1) * 4;        // 0 or 4
            float4 v = *reinterpret_cast<const float4*>(&B[(long)(n0 + nr) * ldb + k0 + kc]);
            Bs[kc + 0][nr] = v.x;
            Bs[kc + 1][nr] = v.y;
            Bs[kc + 2][nr] = v.z;
            Bs[kc + 3][nr] = v.w;
        }
        __syncthreads();

#pragma unroll
        for (int k = 0; k < 8; ++k) {
            float4 a0 = *reinterpret_cast<const float4*>(&As[k][ty * 8]);
            float4 a1 = *reinterpret_cast<const float4*>(&As[k][ty * 8 + 4]);
            float4 b0 = *reinterpret_cast<const float4*>(&Bs[k][tx * 8]);
            float4 b1 = *reinterpret_cast<const float4*>(&Bs[k][tx * 8 + 4]);
            float a[8] = {a0.x, a0.y, a0.z, a0.w, a1.x, a1.y, a1.z, a1.w};
            float bb[8] = {b0.x, b0.y, b0.z, b0.w, b1.x, b1.y, b1.z, b1.w};
#pragma unroll
            for (int i = 0; i < 8; ++i)
#pragma unroll
                for (int j = 0; j < 8; ++j)
                    acc[i][j] = fmaf(a[i], bb[j], acc[i][j]);
        }
        __syncthreads();
    }

#pragma unroll
    for (int i = 0; i < 8; ++i) {
        const int m = m0 + ty * 8 + i;
        const float bv = bias ? bias[m] : 0.f;
#pragma unroll
        for (int j = 0; j < 8; j += 4) {
            float4 o;
            o.x = acc[i][j + 0] + bv;
            o.y = acc[i][j + 1] + bv;
            o.z = acc[i][j + 2] + bv;
            o.w = acc[i][j + 3] + bv;
            *reinterpret_cast<float4*>(&C[(long)m * N + n0 + tx * 8 + j]) = o;
        }
    }
}

// ---------------- softmax over rows of length 512 (in place) -------------------
__global__ void __launch_bounds__(256)
softmax512_kernel(float* __restrict__ f)
{
    float* p = f + (long)blockIdx.x * NN;
    const int t = threadIdx.x;          // 256 threads, 2 elems each
    float v0 = p[t];
    float v1 = p[t + 256];

    __shared__ float red[8];

    // max
    float m = fmaxf(v0, v1);
#pragma unroll
    for (int o = 16; o; o >>= 1) m = fmaxf(m, __shfl_xor_sync(0xffffffffu, m, o));
    if ((t & 31) == 0) red[t >> 5] = m;
    __syncthreads();
    float M = red[0];
#pragma unroll
    for (int i = 1; i < 8; ++i) M = fmaxf(M, red[i]);
    __syncthreads();

    float e0 = expf(v0 - M);
    float e1 = expf(v1 - M);
    float s = e0 + e1;
#pragma unroll
    for (int o = 16; o; o >>= 1) s += __shfl_xor_sync(0xffffffffu, s, o);
    if ((t & 31) == 0) red[t >> 5] = s;
    __syncthreads();
    float S = 0.f;
#pragma unroll
    for (int i = 0; i < 8; ++i) S += red[i];

    const float inv = 1.f / S;
    p[t]       = e0 * inv;
    p[t + 256] = e1 * inv;
}

// ---------------- BN statistics: per-channel mean & rstd over (B, N) ----------
__global__ void __launch_bounds__(256)
bn_stats_kernel(const float* __restrict__ wy, float* __restrict__ mean,
                float* __restrict__ rstd)
{
    const int o = blockIdx.x;           // channel 0..2047
    const int t = threadIdx.x;
    double ds = 0.0, dss = 0.0;
    for (int i = t; i < BB * NN; i += 256) {
        const int b = i >> 9;
        const int n = i & (NN - 1);
        const float v = wy[((long)b * CC + o) * NN + n];
        ds  += (double)v;
        dss += (double)v * (double)v;
    }
    __shared__ double r1[256];
    __shared__ double r2[256];
    r1[t] = ds; r2[t] = dss;
    __syncthreads();
    for (int st = 128; st; st >>= 1) {
        if (t < st) { r1[t] += r1[t + st]; r2[t] += r2[t + st]; }
        __syncthreads();
    }
    if (t == 0) {
        const double cnt = (double)(BB * NN);
        const double mu  = r1[0] / cnt;
        const double var = r2[0] / cnt - mu * mu;
        mean[o] = (float)mu;
        rstd[o] = (float)rsqrt(var + 1e-5);
    }
}

// ---------------- normalize + affine + residual (in place on out) -------------
__global__ void __launch_bounds__(256)
bn_apply_kernel(float* __restrict__ out, const float* __restrict__ x,
                const float* __restrict__ mean, const float* __restrict__ rstd,
                const float* __restrict__ gamma, const float* __restrict__ beta)
{
    const long i4 = (long)blockIdx.x * blockDim.x + threadIdx.x;
    const long e = i4 * 4;
    const int c = (int)((e >> 9) & (CC - 1));   // (e / NN) % CC
    const float mu = mean[c];
    const float rs = rstd[c];
    const float ga = gamma[c];
    const float be = beta[c];
    float4 w  = *reinterpret_cast<const float4*>(&out[e]);
    float4 xv = *reinterpret_cast<const float4*>(&x[e]);
    w.x = (w.x - mu) * rs * ga + be + xv.x;
    w.y = (w.y - mu) * rs * ga + be + xv.y;
    w.z = (w.z - mu) * rs * ga + be + xv.z;
    w.w = (w.w - mu) * rs * ga + be + xv.w;
    *reinterpret_cast<float4*>(&out[e]) = w;
}

// -------------------------------------------------------------------------------
extern "C" void kernel_launch(void* const* d_in, const int* in_sizes, int n_in,
                              void* d_out, int out_size)
{
    const float* x     = (const float*)d_in[0];
    const float* Wg    = (const float*)d_in[1];
    const float* bg    = (const float*)d_in[2];
    const float* Wt    = (const float*)d_in[3];
    const float* bt    = (const float*)d_in[4];
    const float* Wp    = (const float*)d_in[5];
    const float* bp    = (const float*)d_in[6];
    const float* Wo    = (const float*)d_in[7];
    const float* bo    = (const float*)d_in[8];
    const float* gamma = (const float*)d_in[9];
    const float* beta  = (const float*)d_in[10];
    float* out = (float*)d_out;

    float *g, *th, *ph, *f, *y, *mean, *rstd;
    cudaGetSymbolAddress((void**)&g,    g_g);
    cudaGetSymbolAddress((void**)&th,   g_th);
    cudaGetSymbolAddress((void**)&ph,   g_ph);
    cudaGetSymbolAddress((void**)&f,    g_f);
    cudaGetSymbolAddress((void**)&y,    g_y);
    cudaGetSymbolAddress((void**)&mean, g_mean);
    cudaGetSymbolAddress((void**)&rstd, g_rstd);

    const long sXB = (long)CC * NN;     // per-batch stride of x / wy
    const long sPB = (long)CI * NN;     // per-batch stride of g/th/ph/y
    const long sFB = (long)NN * NN;     // per-batch stride of f

    // 1) projections: [Ci x C] @ [C x N] per batch (+bias)
    {
        dim3 grid(NN / 128, CI / 128, BB);
        sgemm_kernel<false, false><<<grid, 256>>>(Wg, x, g,  bg, CI, NN, CC, CC, NN, 0, sXB, sPB);
        sgemm_kernel<false, false><<<grid, 256>>>(Wt, x, th, bt, CI, NN, CC, CC, NN, 0, sXB, sPB);
        sgemm_kernel<false, false><<<grid, 256>>>(Wp, x, ph, bp, CI, NN, CC, CC, NN, 0, sXB, sPB);
    }

    // 2) f[n][m] = sum_c th[c][n] * ph[c][m]   (TN)
    {
        dim3 grid(NN / 128, NN / 128, BB);
        sgemm_kernel<true, false><<<grid, 256>>>(th, ph, f, nullptr, NN, NN, CI, NN, NN, sPB, sPB, sFB);
    }

    // 3) softmax over last dim (rows of length 512)
    softmax512_kernel<<<BB * NN, 256>>>(f);

    // 4) y[c][n] = sum_m g[c][m] * attn[n][m]   (NT)
    {
        dim3 grid(NN / 128, CI / 128, BB);
        sgemm_kernel<false, true><<<grid, 256>>>(g, f, y, nullptr, CI, NN, NN, NN, NN, sPB, sFB, sPB);
    }

    // 5) wy = Wo @ y + bo  -> d_out
    {
        dim3 grid(NN / 128, CC / 128, BB);
        sgemm_kernel<false, false><<<grid, 256>>>(Wo, y, out, bo, CC, NN, CI, CI, NN, 0, sPB, sXB);
    }

    // 6) BN stats per channel
    bn_stats_kernel<<<CC, 256>>>(out, mean, rstd);

    // 7) normalize + affine + residual (in place)
    {
        const long total4 = (long)BB * CC * NN / 4;   // 16,777,216
        bn_apply_kernel<<<(unsigned)(total4 / 256), 256>>>(out, x, mean, rstd, gamma, beta);
    }
}

// round 3
// speedup vs baseline: 1.7062x; 1.7062x over previous
#include <cuda_runtime.h>
#include <cuda_bf16.h>
#include <cstdint>
#include <math.h>

#define BB 64
#define CC 2048
#define CI 1024
#define NSP 512   // H*W

typedef __nv_bfloat16 bf16;

// ---------------- scratch (static device globals) -----------------------------
__device__ bf16 g_xT_h [(size_t)BB * NSP * CC];
__device__ bf16 g_xT_l [(size_t)BB * NSP * CC];
__device__ bf16 g_Wg_h [(size_t)CI * CC];
__device__ bf16 g_Wg_l [(size_t)CI * CC];
__device__ bf16 g_Wt_h [(size_t)CI * CC];
__device__ bf16 g_Wt_l [(size_t)CI * CC];
__device__ bf16 g_Wp_h [(size_t)CI * CC];
__device__ bf16 g_Wp_l [(size_t)CI * CC];
__device__ bf16 g_Wo_h [(size_t)CC * CI];
__device__ bf16 g_Wo_l [(size_t)CC * CI];
__device__ bf16 g_g_h  [(size_t)BB * CI * NSP];
__device__ bf16 g_g_l  [(size_t)BB * CI * NSP];
__device__ bf16 g_thT_h[(size_t)BB * NSP * CI];
__device__ bf16 g_thT_l[(size_t)BB * NSP * CI];
__device__ bf16 g_phT_h[(size_t)BB * NSP * CI];
__device__ bf16 g_phT_l[(size_t)BB * NSP * CI];
__device__ bf16 g_yT_h [(size_t)BB * NSP * CI];
__device__ bf16 g_yT_l [(size_t)BB * NSP * CI];
__device__ float g_f   [(size_t)BB * NSP * NSP];
__device__ bf16 g_at_h [(size_t)BB * NSP * NSP];
__device__ bf16 g_at_l [(size_t)BB * NSP * NSP];
__device__ float g_mean[CC];
__device__ float g_rstd[CC];

// ---------------- helpers ------------------------------------------------------
__device__ __forceinline__ void split2(float v0, float v1, unsigned& uh, unsigned& ul) {
    bf16 h0 = __float2bfloat16(v0);
    bf16 h1 = __float2bfloat16(v1);
    bf16 l0 = __float2bfloat16(v0 - __bfloat162float(h0));
    bf16 l1 = __float2bfloat16(v1 - __bfloat162float(h1));
    uh = ((unsigned)__bfloat16_as_ushort(h1) << 16) | (unsigned)__bfloat16_as_ushort(h0);
    ul = ((unsigned)__bfloat16_as_ushort(l1) << 16) | (unsigned)__bfloat16_as_ushort(l0);
}

__device__ __forceinline__ uint32_t smem_u32(const void* p) {
    uint32_t a;
    asm("{ .reg .u64 t; cvta.to.shared.u64 t, %1; cvt.u32.u64 %0, t; }" : "=r"(a) : "l"(p));
    return a;
}

__device__ __forceinline__ void ldsm_x4(uint32_t* r, uint32_t addr) {
    asm volatile("ldmatrix.sync.aligned.m8n8.x4.shared.b16 {%0,%1,%2,%3}, [%4];"
                 : "=r"(r[0]), "=r"(r[1]), "=r"(r[2]), "=r"(r[3]) : "r"(addr));
}
__device__ __forceinline__ void ldsm_x2(uint32_t* r, uint32_t addr) {
    asm volatile("ldmatrix.sync.aligned.m8n8.x2.shared.b16 {%0,%1}, [%2];"
                 : "=r"(r[0]), "=r"(r[1]) : "r"(addr));
}
__device__ __forceinline__ void mma16816(float* c, const uint32_t* a, const uint32_t* b) {
    asm volatile("mma.sync.aligned.m16n8k16.row.col.f32.bf16.bf16.f32 "
                 "{%0,%1,%2,%3}, {%4,%5,%6,%7}, {%8,%9}, {%0,%1,%2,%3};"
                 : "+f"(c[0]), "+f"(c[1]), "+f"(c[2]), "+f"(c[3])
                 : "r"(a[0]), "r"(a[1]), "r"(a[2]), "r"(a[3]), "r"(b[0]), "r"(b[1]));
}

// copy one 32-k-element chunk of a 128-row operand into blocked smem layout
// blocked: tile(k8, r8) at ((k8*16 + r8)*128) bytes, row-in-tile*16
__device__ __forceinline__ void cpa(uint32_t dst, const bf16* __restrict__ src,
                                    int ld, int k0, int tid) {
#pragma unroll
    for (int it = 0; it < 2; ++it) {
        int u  = tid + it * 256;          // 0..511
        int kb = u >> 7;                  // 0..3 (8-elem k block)
        int r  = u & 127;
        const void* gp = src + (size_t)r * ld + k0 + kb * 8;
        uint32_t dp = dst + (uint32_t)((((kb << 4) + (r >> 3)) << 7) + ((r & 7) << 4));
        asm volatile("cp.async.cg.shared.global [%0], [%1], 16;" :: "r"(dp), "l"(gp));
    }
}

// ---------------- HMMA GEMM: D[m][n] = sum_k (Ah+Al)[m][k]*(Bh+Bl)[n][k] ------
// CTA tile 128x128, 8 warps (2m x 4n), warp tile 64x32, k-chunk 32, 3 stages.
// BIAS: 0 none, 1 per-row (M), 2 per-col (N).  OUTHILO: 0 fp32, 1 hi/lo bf16.
template<int BIAS, int OUTHILO>
__global__ void __launch_bounds__(256)
hmma_gemm(const bf16* __restrict__ Ah, const bf16* __restrict__ Al,
          const bf16* __restrict__ Bh, const bf16* __restrict__ Bl,
          void* __restrict__ Co, bf16* __restrict__ Colo,
          const float* __restrict__ bias,
          int K, int ldo, long bsA, long bsB, long bsC)
{
    extern __shared__ char smem[];
    const uint32_t sm0 = smem_u32(smem);

    const int tid = threadIdx.x, wid = tid >> 5, lane = tid & 31;
    const int wm = wid >> 2, wn = wid & 3;          // warp grid 2x4
    const int m0 = blockIdx.y * 128, n0 = blockIdx.x * 128, b = blockIdx.z;

    const bf16* pAh = Ah + (size_t)b * bsA + (size_t)m0 * K;
    const bf16* pAl = Al + (size_t)b * bsA + (size_t)m0 * K;
    const bf16* pBh = Bh + (size_t)b * bsB + (size_t)n0 * K;
    const bf16* pBl = Bl + (size_t)b * bsB + (size_t)n0 * K;

    const int nch = K >> 5;

    float acc[4][4][4];
#pragma unroll
    for (int i = 0; i < 4; ++i)
#pragma unroll
        for (int j = 0; j < 4; ++j)
#pragma unroll
            for (int q = 0; q < 4; ++q) acc[i][j][q] = 0.f;

    // prologue: prefetch chunks 0 and 1
#pragma unroll
    for (int p = 0; p < 2; ++p) {
        uint32_t sb = sm0 + (p % 3) * 32768;
        cpa(sb + 0,     pAh, K, p * 32, tid);
        cpa(sb + 8192,  pAl, K, p * 32, tid);
        cpa(sb + 16384, pBh, K, p * 32, tid);
        cpa(sb + 24576, pBl, K, p * 32, tid);
        asm volatile("cp.async.commit_group;");
    }

    const int mbase8 = wm * 8;          // /8 units within 128-row A tile
    const int nbase8 = wn * 4;          // /8 units within 128-row B tile
    const int lrow = lane & 7;
    const int ga = lane >> 3;           // 0..3 for x4
    const int gb = (lane >> 3) & 1;     // 0..1 for x2

    for (int ks = 0; ks < nch; ++ks) {
        asm volatile("cp.async.wait_group 1;" ::: "memory");
        __syncthreads();

        // prefetch ks+2 into stage (ks+2)%3 (that stage was consumed at ks-1)
        {
            const int pf = ks + 2;
            if (pf < nch) {
                uint32_t sb = sm0 + (pf % 3) * 32768;
                cpa(sb + 0,     pAh, K, pf * 32, tid);
                cpa(sb + 8192,  pAl, K, pf * 32, tid);
                cpa(sb + 16384, pBh, K, pf * 32, tid);
                cpa(sb + 24576, pBl, K, pf * 32, tid);
            }
            asm volatile("cp.async.commit_group;");
        }

        const uint32_t sb = sm0 + (ks % 3) * 32768;
#pragma unroll
        for (int kk = 0; kk < 2; ++kk) {
            uint32_t a_h[4][4], a_l[4][4];
#pragma unroll
            for (int mf = 0; mf < 4; ++mf) {
                const int k8 = 2 * kk + (ga >> 1);
                const int m8 = mbase8 + mf * 2 + (ga & 1);
                uint32_t addr = sb + (uint32_t)(((k8 * 16 + m8) * 128) + lrow * 16);
                ldsm_x4(a_h[mf], addr);
                ldsm_x4(a_l[mf], addr + 8192);
            }
#pragma unroll
            for (int nf = 0; nf < 4; ++nf) {
                uint32_t b_h[2], b_l[2];
                const int k8 = 2 * kk + gb;
                const int n8 = nbase8 + nf;
                uint32_t addr = sb + 16384 + (uint32_t)(((k8 * 16 + n8) * 128) + lrow * 16);
                ldsm_x2(b_h, addr);
                ldsm_x2(b_l, addr + 8192);
#pragma unroll
                for (int mf = 0; mf < 4; ++mf) {
                    mma16816(acc[mf][nf], a_h[mf], b_h);
                    mma16816(acc[mf][nf], a_l[mf], b_h);
                    mma16816(acc[mf][nf], a_h[mf], b_l);
                }
            }
        }
    }

    // ---- epilogue (natural row-major) ----
    const int erow = lane >> 2;
    const int ecol = (lane & 3) * 2;
#pragma unroll
    for (int mf = 0; mf < 4; ++mf) {
        const int gm = m0 + wm * 64 + mf * 16 + erow;
        float rb0 = 0.f, rb1 = 0.f;
        if (BIAS == 1) { rb0 = bias[gm]; rb1 = bias[gm + 8]; }
#pragma unroll
        for (int nf = 0; nf < 4; ++nf) {
            const int gn = n0 + wn * 32 + nf * 8 + ecol;
            float cb0 = 0.f, cb1 = 0.f;
            if (BIAS == 2) { cb0 = bias[gn]; cb1 = bias[gn + 1]; }
            float v00 = acc[mf][nf][0] + rb0 + cb0;
            float v01 = acc[mf][nf][1] + rb0 + cb1;
            float v10 = acc[mf][nf][2] + rb1 + cb0;
            float v11 = acc[mf][nf][3] + rb1 + cb1;
            if (OUTHILO == 0) {
                float* C = (float*)Co + (size_t)b * bsC + (size_t)gm * ldo + gn;
                *reinterpret_cast<float2*>(C) = make_float2(v00, v01);
                *reinterpret_cast<float2*>(C + 8 * (size_t)ldo) = make_float2(v10, v11);
            } else {
                bf16* Ch = (bf16*)Co + (size_t)b * bsC + (size_t)gm * ldo + gn;
                bf16* Cl = Colo      + (size_t)b * bsC + (size_t)gm * ldo + gn;
                unsigned uh, ul;
                split2(v00, v01, uh, ul);
                *reinterpret_cast<unsigned*>(Ch) = uh;
                *reinterpret_cast<unsigned*>(Cl) = ul;
                split2(v10, v11, uh, ul);
                *reinterpret_cast<unsigned*>(Ch + 8 * (size_t)ldo) = uh;
                *reinterpret_cast<unsigned*>(Cl + 8 * (size_t)ldo) = ul;
            }
        }
    }
}

// ---------------- pre-pass: fp32 -> bf16 hi/lo ----------------------------------
__global__ void __launch_bounds__(256)
split_kernel(const float* __restrict__ s, bf16* __restrict__ dh,
             bf16* __restrict__ dl, int n) {
    int i = blockIdx.x * 256 + threadIdx.x;
    if (i < n) {
        float v = s[i];
        bf16 h = __float2bfloat16(v);
        dh[i] = h;
        dl[i] = __float2bfloat16(v - __bfloat162float(h));
    }
}

// x [b][c][n] -> xT hi/lo [b][n][c]
__global__ void __launch_bounds__(256)
xpose_split_kernel(const float* __restrict__ x, bf16* __restrict__ th,
                   bf16* __restrict__ tl) {
    __shared__ float t[32][33];
    const int b = blockIdx.z;
    const int n0 = blockIdx.x * 32, c0 = blockIdx.y * 32;
    const int tx = threadIdx.x & 31, ty = threadIdx.x >> 5;
    const float* xp = x + ((size_t)b * CC + c0) * NSP + n0;
#pragma unroll
    for (int i = 0; i < 4; ++i)
        t[ty + i * 8][tx] = xp[(size_t)(ty + i * 8) * NSP + tx];
    __syncthreads();
    const size_t ob = ((size_t)b * NSP + n0) * CC + c0;
#pragma unroll
    for (int i = 0; i < 4; ++i) {
        float v = t[tx][ty + i * 8];
        bf16 h = __float2bfloat16(v);
        th[ob + (size_t)(ty + i * 8) * CC + tx] = h;
        tl[ob + (size_t)(ty + i * 8) * CC + tx] = __float2bfloat16(v - __bfloat162float(h));
    }
}

// ---------------- softmax over rows of 512 -> hi/lo bf16 -----------------------
__global__ void __launch_bounds__(256)
softmax_split_kernel(const float* __restrict__ f, bf16* __restrict__ ah,
                     bf16* __restrict__ al) {
    const size_t off = (size_t)blockIdx.x * NSP;
    const float* p = f + off;
    const int t = threadIdx.x;
    float v0 = p[t];
    float v1 = p[t + 256];

    __shared__ float red[8];
    float m = fmaxf(v0, v1);
#pragma unroll
    for (int o = 16; o; o >>= 1) m = fmaxf(m, __shfl_xor_sync(0xffffffffu, m, o));
    if ((t & 31) == 0) red[t >> 5] = m;
    __syncthreads();
    float M = red[0];
#pragma unroll
    for (int i = 1; i < 8; ++i) M = fmaxf(M, red[i]);
    __syncthreads();

    float e0 = expf(v0 - M);
    float e1 = expf(v1 - M);
    float s = e0 + e1;
#pragma unroll
    for (int o = 16; o; o >>= 1) s += __shfl_xor_sync(0xffffffffu, s, o);
    if ((t & 31) == 0) red[t >> 5] = s;
    __syncthreads();
    float S = 0.f;
#pragma unroll
    for (int i = 0; i < 8; ++i) S += red[i];

    const float inv = 1.f / S;
    float a0 = e0 * inv, a1 = e1 * inv;
    bf16 h0 = __float2bfloat16(a0);
    bf16 h1 = __float2bfloat16(a1);
    ah[off + t]       = h0;
    ah[off + t + 256] = h1;
    al[off + t]       = __float2bfloat16(a0 - __bfloat162float(h0));
    al[off + t + 256] = __float2bfloat16(a1 - __bfloat162float(h1));
}

// ---------------- BN stats & apply ----------------------------------------------
__global__ void __launch_bounds__(256)
bn_stats_kernel(const float* __restrict__ wy, float* __restrict__ mean,
                float* __restrict__ rstd) {
    const int o = blockIdx.x;
    const int t = threadIdx.x;
    double ds = 0.0, dss = 0.0;
    for (int i = t; i < BB * NSP; i += 256) {
        const int b = i >> 9;
        const int n = i & (NSP - 1);
        const float v = wy[((size_t)b * CC + o) * NSP + n];
        ds  += (double)v;
        dss += (double)v * (double)v;
    }
    __shared__ double r1[256];
    __shared__ double r2[256];
    r1[t] = ds; r2[t] = dss;
    __syncthreads();
    for (int st = 128; st; st >>= 1) {
        if (t < st) { r1[t] += r1[t + st]; r2[t] += r2[t + st]; }
        __syncthreads();
    }
    if (t == 0) {
        const double cnt = (double)(BB * NSP);
        const double mu  = r1[0] / cnt;
        const double var = r2[0] / cnt - mu * mu;
        mean[o] = (float)mu;
        rstd[o] = (float)rsqrt(var + 1e-5);
    }
}

__global__ void __launch_bounds__(256)
bn_apply_kernel(float* __restrict__ out, const float* __restrict__ x,
                const float* __restrict__ mean, const float* __restrict__ rstd,
                const float* __restrict__ gamma, const float* __restrict__ beta) {
    const long i4 = (long)blockIdx.x * blockDim.x + threadIdx.x;
    const long e = i4 * 4;
    const int c = (int)((e >> 9) & (CC - 1));
    const float mu = mean[c];
    const float rs = rstd[c];
    const float ga = gamma[c];
    const float be = beta[c];
    float4 w  = *reinterpret_cast<const float4*>(&out[e]);
    float4 xv = *reinterpret_cast<const float4*>(&x[e]);
    w.x = (w.x - mu) * rs * ga + be + xv.x;
    w.y = (w.y - mu) * rs * ga + be + xv.y;
    w.z = (w.z - mu) * rs * ga + be + xv.z;
    w.w = (w.w - mu) * rs * ga + be + xv.w;
    *reinterpret_cast<float4*>(&out[e]) = w;
}

// -------------------------------------------------------------------------------
extern "C" void kernel_launch(void* const* d_in, const int* in_sizes, int n_in,
                              void* d_out, int out_size)
{
    const float* x     = (const float*)d_in[0];
    const float* Wg    = (const float*)d_in[1];
    const float* bg    = (const float*)d_in[2];
    const float* Wt    = (const float*)d_in[3];
    const float* bt    = (const float*)d_in[4];
    const float* Wp    = (const float*)d_in[5];
    const float* bp    = (const float*)d_in[6];
    const float* Wo    = (const float*)d_in[7];
    const float* bo    = (const float*)d_in[8];
    const float* gamma = (const float*)d_in[9];
    const float* beta  = (const float*)d_in[10];
    float* out = (float*)d_out;

    bf16 *xTh, *xTl, *Wgh, *Wgl, *Wth, *Wtl, *Wph, *Wpl, *Woh, *Wol;
    bf16 *gh, *gl, *thh, *thl, *phh, *phl, *yh, *yl, *ath, *atl;
    float *f, *mean, *rstd;
    cudaGetSymbolAddress((void**)&xTh, g_xT_h);   cudaGetSymbolAddress((void**)&xTl, g_xT_l);
    cudaGetSymbolAddress((void**)&Wgh, g_Wg_h);   cudaGetSymbolAddress((void**)&Wgl, g_Wg_l);
    cudaGetSymbolAddress((void**)&Wth, g_Wt_h);   cudaGetSymbolAddress((void**)&Wtl, g_Wt_l);
    cudaGetSymbolAddress((void**)&Wph, g_Wp_h);   cudaGetSymbolAddress((void**)&Wpl, g_Wp_l);
    cudaGetSymbolAddress((void**)&Woh, g_Wo_h);   cudaGetSymbolAddress((void**)&Wol, g_Wo_l);
    cudaGetSymbolAddress((void**)&gh,  g_g_h);    cudaGetSymbolAddress((void**)&gl,  g_g_l);
    cudaGetSymbolAddress((void**)&thh, g_thT_h);  cudaGetSymbolAddress((void**)&thl, g_thT_l);
    cudaGetSymbolAddress((void**)&phh, g_phT_h);  cudaGetSymbolAddress((void**)&phl, g_phT_l);
    cudaGetSymbolAddress((void**)&yh,  g_yT_h);   cudaGetSymbolAddress((void**)&yl,  g_yT_l);
    cudaGetSymbolAddress((void**)&ath, g_at_h);   cudaGetSymbolAddress((void**)&atl, g_at_l);
    cudaGetSymbolAddress((void**)&f,   g_f);
    cudaGetSymbolAddress((void**)&mean, g_mean);  cudaGetSymbolAddress((void**)&rstd, g_rstd);

    const int SM = 3 * 32768;
    cudaFuncSetAttribute((const void*)hmma_gemm<0,0>, cudaFuncAttributeMaxDynamicSharedMemorySize, SM);
    cudaFuncSetAttribute((const void*)hmma_gemm<0,1>, cudaFuncAttributeMaxDynamicSharedMemorySize, SM);
    cudaFuncSetAttribute((const void*)hmma_gemm<1,0>, cudaFuncAttributeMaxDynamicSharedMemorySize, SM);
    cudaFuncSetAttribute((const void*)hmma_gemm<1,1>, cudaFuncAttributeMaxDynamicSharedMemorySize, SM);
    cudaFuncSetAttribute((const void*)hmma_gemm<2,1>, cudaFuncAttributeMaxDynamicSharedMemorySize, SM);

    // ---- pre-pass: split weights, transpose+split x
    {
        const int nw = CI * CC;
        split_kernel<<<(nw + 255) / 256, 256>>>(Wg, Wgh, Wgl, nw);
        split_kernel<<<(nw + 255) / 256, 256>>>(Wt, Wth, Wtl, nw);
        split_kernel<<<(nw + 255) / 256, 256>>>(Wp, Wph, Wpl, nw);
        split_kernel<<<(nw + 255) / 256, 256>>>(Wo, Woh, Wol, nw);
    }
    xpose_split_kernel<<<dim3(NSP / 32, CC / 32, BB), 256>>>(x, xTh, xTl);

    const long bs_xT = (long)NSP * CC;
    const long bs_pT = (long)NSP * CI;
    const long bs_gN = (long)CI * NSP;
    const long bs_f  = (long)NSP * NSP;
    const long bs_o  = (long)CC * NSP;

    // 1) g[ci][n] = Wg[ci][:] . xT[n][:] + bg  (K=2048, row bias, hi/lo out)
    hmma_gemm<1,1><<<dim3(NSP/128, CI/128, BB), 256, SM>>>(
        Wgh, Wgl, xTh, xTl, gh, gl, bg, CC, NSP, 0L, bs_xT, bs_gN);
    // 2) thT[n][ci] = xT[n][:] . Wt[ci][:] + bt  (col bias)
    hmma_gemm<2,1><<<dim3(CI/128, NSP/128, BB), 256, SM>>>(
        xTh, xTl, Wth, Wtl, thh, thl, bt, CC, CI, bs_xT, 0L, bs_pT);
    // 3) phT
    hmma_gemm<2,1><<<dim3(CI/128, NSP/128, BB), 256, SM>>>(
        xTh, xTl, Wph, Wpl, phh, phl, bp, CC, CI, bs_xT, 0L, bs_pT);
    // 4) f[n][m] = thT[n][:] . phT[m][:]  (fp32 out)
    hmma_gemm<0,0><<<dim3(NSP/128, NSP/128, BB), 256, SM>>>(
        thh, thl, phh, phl, f, nullptr, nullptr, CI, NSP, bs_pT, bs_pT, bs_f);
    // softmax -> hi/lo attn
    softmax_split_kernel<<<BB * NSP, 256>>>(f, ath, atl);
    // 5) yT[n][ci] = attn[n][:] . g[ci][:]  (K=512)
    hmma_gemm<0,1><<<dim3(CI/128, NSP/128, BB), 256, SM>>>(
        ath, atl, gh, gl, yh, yl, nullptr, NSP, CI, bs_f, bs_gN, bs_pT);
    // 6) out[o][n] = Wo[o][:] . yT[n][:] + bo  (fp32 -> d_out)
    hmma_gemm<1,0><<<dim3(NSP/128, CC/128, BB), 256, SM>>>(
        Woh, Wol, yh, yl, out, nullptr, bo, CI, NSP, 0L, bs_pT, bs_o);

    // ---- BN stats + apply + residual
    bn_stats_kernel<<<CC, 256>>>(out, mean, rstd);
    {
        const long total4 = (long)BB * CC * NSP / 4;
        bn_apply_kernel<<<(unsigned)(total4 / 256), 256>>>(out, x, mean, rstd, gamma, beta);
    }
}

// round 4
// speedup vs baseline: 2.0520x; 1.2026x over previous
#include <cuda_runtime.h>
#include <cuda_bf16.h>
#include <cuda_fp16.h>
#include <cstdint>
#include <math.h>

#define BB 64
#define CC 2048
#define CI 1024
#define NSP 512   // H*W

typedef unsigned short u16;
typedef uint32_t u32;

// ---------------- scratch (static device globals) -----------------------------
__device__ u16 g_xTbh[(size_t)BB * NSP * CC];   // x^T bf16 hi  [b][n][c]
__device__ u16 g_xTbl[(size_t)BB * NSP * CC];   // x^T bf16 lo
__device__ u16 g_xTf [(size_t)BB * NSP * CC];   // x^T fp16 single
__device__ u16 g_Wth[(size_t)CI * CC], g_Wtl[(size_t)CI * CC];   // bf16 h/l
__device__ u16 g_Wph[(size_t)CI * CC], g_Wpl[(size_t)CI * CC];   // bf16 h/l
__device__ u16 g_Wgh[(size_t)CI * CC], g_Wgl[(size_t)CI * CC];   // fp16 h/l
__device__ u16 g_Woh[(size_t)CC * CI], g_Wol[(size_t)CC * CI];   // fp16 h/l
__device__ u16 g_thh[(size_t)BB * NSP * CI], g_thl[(size_t)BB * NSP * CI]; // bf16
__device__ u16 g_phh[(size_t)BB * NSP * CI], g_phl[(size_t)BB * NSP * CI]; // bf16
__device__ u16 g_gf [(size_t)BB * CI * NSP];    // g fp16 single [b][ci][m]
__device__ float g_f [(size_t)BB * NSP * NSP];  // f fp32
__device__ u16 g_ath[(size_t)BB * NSP * NSP], g_atl[(size_t)BB * NSP * NSP]; // attn fp16 h/l
__device__ u16 g_yT [(size_t)BB * NSP * CI];    // y^T fp16 single [b][n][ci]
__device__ float g_mean[CC];
__device__ float g_rstd[CC];

// ---------------- helpers ------------------------------------------------------
__device__ __forceinline__ u32 smem_u32(const void* p) {
    u32 a;
    asm("{ .reg .u64 t; cvta.to.shared.u64 t, %1; cvt.u32.u64 %0, t; }" : "=r"(a) : "l"(p));
    return a;
}
__device__ __forceinline__ void split_bf(float v, u16& h, u16& l) {
    __nv_bfloat16 bh = __float2bfloat16(v);
    h = __bfloat16_as_ushort(bh);
    l = __bfloat16_as_ushort(__float2bfloat16(v - __bfloat162float(bh)));
}
__device__ __forceinline__ void split_fp(float v, u16& h, u16& l) {
    __half hh = __float2half_rn(v);
    h = __half_as_ushort(hh);
    l = __half_as_ushort(__float2half_rn(v - __half2float(hh)));
}
__device__ __forceinline__ void ldsm_x4(u32* r, u32 addr) {
    asm volatile("ldmatrix.sync.aligned.m8n8.x4.shared.b16 {%0,%1,%2,%3}, [%4];"
                 : "=r"(r[0]), "=r"(r[1]), "=r"(r[2]), "=r"(r[3]) : "r"(addr));
}
template<int FP16>
__device__ __forceinline__ void mma16816(float* c, const u32* a, const u32* b) {
    if (FP16)
        asm volatile("mma.sync.aligned.m16n8k16.row.col.f32.f16.f16.f32 "
                     "{%0,%1,%2,%3}, {%4,%5,%6,%7}, {%8,%9}, {%0,%1,%2,%3};"
                     : "+f"(c[0]), "+f"(c[1]), "+f"(c[2]), "+f"(c[3])
                     : "r"(a[0]), "r"(a[1]), "r"(a[2]), "r"(a[3]), "r"(b[0]), "r"(b[1]));
    else
        asm volatile("mma.sync.aligned.m16n8k16.row.col.f32.bf16.bf16.f32 "
                     "{%0,%1,%2,%3}, {%4,%5,%6,%7}, {%8,%9}, {%0,%1,%2,%3};"
                     : "+f"(c[0]), "+f"(c[1]), "+f"(c[2]), "+f"(c[3])
                     : "r"(a[0]), "r"(a[1]), "r"(a[2]), "r"(a[3]), "r"(b[0]), "r"(b[1]));
}

// copy ROWSx32 u16 chunk (row stride = K) into blocked smem: tile(kb, r8) at
// ((kb*ROWS/8 + r8)*128) + (r&7)*16. 4 consecutive threads read 64B contiguous.
template<int ROWS>
__device__ __forceinline__ void cpa(u32 dst, const u16* __restrict__ src,
                                    int K, int k0, int tid) {
    constexpr int RT  = ROWS / 8;
    constexpr int PER = (ROWS * 4) / 256;
#pragma unroll
    for (int i = 0; i < PER; ++i) {
        int u  = tid + i * 256;
        int r  = u >> 2;
        int kb = u & 3;
        const void* gp = src + (size_t)r * K + k0 + kb * 8;
        u32 dp = dst + (u32)(((kb * RT + (r >> 3)) << 7) + ((r & 7) << 4));
        asm volatile("cp.async.cg.shared.global [%0], [%1], 16;" :: "r"(dp), "l"(gp));
    }
}

// ---------------- HMMA GEMM -----------------------------------------------------
// D[m][n] = sum_k A[m][k] * B[n][k], A always hi/lo split.
// NMMA=3: B split too (AhBh + AlBh + AhBl).  NMMA=2: B single (AhBh + AlBh).
// CTA 128x256, 8 warps (2m x 4n), warp 64x64, k-chunk 32, 3 stages.
// OUT: 0 fp32, 1 dtype hi/lo pair, 2 dtype single.  BIAS: 0 none, 1 row(M), 2 col(N).
template<int FP16, int NMMA, int OUT, int BIAS>
__global__ void __launch_bounds__(256, 1)
hgemm(const u16* __restrict__ Ah, const u16* __restrict__ Al,
      const u16* __restrict__ Bh, const u16* __restrict__ Bl,
      void* __restrict__ Co, u16* __restrict__ Colo,
      const float* __restrict__ bias,
      int K, int ldo, long bsA, long bsB, long bsC)
{
    extern __shared__ char smem[];
    const u32 sm0 = smem_u32(smem);
    constexpr u32 STAGE = (NMMA == 3) ? 49152u : 32768u;

    const int tid = threadIdx.x, lane = tid & 31, wid = tid >> 5;
    const int wm = wid >> 2, wn = wid & 3;
    const int m0 = blockIdx.y * 128, n0 = blockIdx.x * 256, b = blockIdx.z;

    const u16* pAh = Ah + (size_t)b * bsA + (size_t)m0 * K;
    const u16* pAl = Al + (size_t)b * bsA + (size_t)m0 * K;
    const u16* pBh = Bh + (size_t)b * bsB + (size_t)n0 * K;
    const u16* pBl = (NMMA == 3) ? (Bl + (size_t)b * bsB + (size_t)n0 * K) : nullptr;

    const int nch = K >> 5;

    float acc[4][8][4];
#pragma unroll
    for (int i = 0; i < 4; ++i)
#pragma unroll
        for (int j = 0; j < 8; ++j)
#pragma unroll
            for (int q = 0; q < 4; ++q) acc[i][j][q] = 0.f;

#pragma unroll
    for (int p = 0; p < 2; ++p) {
        u32 sb = sm0 + (u32)(p % 3) * STAGE;
        cpa<128>(sb,         pAh, K, p * 32, tid);
        cpa<128>(sb + 8192,  pAl, K, p * 32, tid);
        cpa<256>(sb + 16384, pBh, K, p * 32, tid);
        if (NMMA == 3) cpa<256>(sb + 32768, pBl, K, p * 32, tid);
        asm volatile("cp.async.commit_group;");
    }

    const int ga = lane >> 3;
    const int lrow = lane & 7;

    for (int ks = 0; ks < nch; ++ks) {
        asm volatile("cp.async.wait_group 1;" ::: "memory");
        __syncthreads();
        {
            const int pf = ks + 2;
            if (pf < nch) {
                u32 sb = sm0 + (u32)(pf % 3) * STAGE;
                cpa<128>(sb,         pAh, K, pf * 32, tid);
                cpa<128>(sb + 8192,  pAl, K, pf * 32, tid);
                cpa<256>(sb + 16384, pBh, K, pf * 32, tid);
                if (NMMA == 3) cpa<256>(sb + 32768, pBl, K, pf * 32, tid);
            }
            asm volatile("cp.async.commit_group;");
        }

        const u32 sb = sm0 + (u32)(ks % 3) * STAGE;
#pragma unroll
        for (int kk = 0; kk < 2; ++kk) {
            u32 ah[4][4], al[4][4];
#pragma unroll
            for (int mf = 0; mf < 4; ++mf) {
                const int k8 = 2 * kk + (ga >> 1);
                const int m8 = wm * 8 + mf * 2 + (ga & 1);
                u32 ad = sb + (u32)(((k8 * 16 + m8) << 7) + (lrow << 4));
                ldsm_x4(ah[mf], ad);
                ldsm_x4(al[mf], ad + 8192);
            }
            u32 bh[8][2], bl[8][2];
#pragma unroll
            for (int np = 0; np < 4; ++np) {
                const int k8 = 2 * kk + (ga >> 1);
                const int n8 = wn * 8 + np * 2 + (ga & 1);
                u32 bd = sb + 16384u + (u32)(((k8 * 32 + n8) << 7) + (lrow << 4));
                u32 t[4];
                ldsm_x4(t, bd);
                bh[2*np][0] = t[0]; bh[2*np][1] = t[2];
                bh[2*np+1][0] = t[1]; bh[2*np+1][1] = t[3];
                if (NMMA == 3) {
                    ldsm_x4(t, bd + 16384u);
                    bl[2*np][0] = t[0]; bl[2*np][1] = t[2];
                    bl[2*np+1][0] = t[1]; bl[2*np+1][1] = t[3];
                }
            }
#pragma unroll
            for (int mf = 0; mf < 4; ++mf)
#pragma unroll
                for (int nf = 0; nf < 8; ++nf) {
                    mma16816<FP16>(acc[mf][nf], ah[mf], bh[nf]);
                    mma16816<FP16>(acc[mf][nf], al[mf], bh[nf]);
                    if (NMMA == 3) mma16816<FP16>(acc[mf][nf], ah[mf], bl[nf]);
                }
        }
    }

    // ---- epilogue ----
    const int erow = lane >> 2;
    const int ecol = (lane & 3) * 2;
#pragma unroll
    for (int mf = 0; mf < 4; ++mf) {
        const int gm = m0 + wm * 64 + mf * 16 + erow;
        float rb0 = 0.f, rb1 = 0.f;
        if (BIAS == 1) { rb0 = bias[gm]; rb1 = bias[gm + 8]; }
#pragma unroll
        for (int nf = 0; nf < 8; ++nf) {
            const int gn = n0 + wn * 64 + nf * 8 + ecol;
            float cb0 = 0.f, cb1 = 0.f;
            if (BIAS == 2) { cb0 = bias[gn]; cb1 = bias[gn + 1]; }
            float v00 = acc[mf][nf][0] + rb0 + cb0;
            float v01 = acc[mf][nf][1] + rb0 + cb1;
            float v10 = acc[mf][nf][2] + rb1 + cb0;
            float v11 = acc[mf][nf][3] + rb1 + cb1;
            if (OUT == 0) {
                float* C = (float*)Co + (size_t)b * bsC + (size_t)gm * ldo + gn;
                *reinterpret_cast<float2*>(C) = make_float2(v00, v01);
                *reinterpret_cast<float2*>(C + 8 * (size_t)ldo) = make_float2(v10, v11);
            } else if (OUT == 1) {
                u16* Ch = (u16*)Co + (size_t)b * bsC + (size_t)gm * ldo + gn;
                u16* Cl = Colo     + (size_t)b * bsC + (size_t)gm * ldo + gn;
                u16 h0, l0, h1, l1;
                if (FP16) { split_fp(v00, h0, l0); split_fp(v01, h1, l1); }
                else      { split_bf(v00, h0, l0); split_bf(v01, h1, l1); }
                *reinterpret_cast<u32*>(Ch) = (u32)h0 | ((u32)h1 << 16);
                *reinterpret_cast<u32*>(Cl) = (u32)l0 | ((u32)l1 << 16);
                if (FP16) { split_fp(v10, h0, l0); split_fp(v11, h1, l1); }
                else      { split_bf(v10, h0, l0); split_bf(v11, h1, l1); }
                *reinterpret_cast<u32*>(Ch + 8 * (size_t)ldo) = (u32)h0 | ((u32)h1 << 16);
                *reinterpret_cast<u32*>(Cl + 8 * (size_t)ldo) = (u32)l0 | ((u32)l1 << 16);
            } else {
                u16* C = (u16*)Co + (size_t)b * bsC + (size_t)gm * ldo + gn;
                u16 h0 = __half_as_ushort(__float2half_rn(v00));
                u16 h1 = __half_as_ushort(__float2half_rn(v01));
                *reinterpret_cast<u32*>(C) = (u32)h0 | ((u32)h1 << 16);
                h0 = __half_as_ushort(__float2half_rn(v10));
                h1 = __half_as_ushort(__float2half_rn(v11));
                *reinterpret_cast<u32*>(C + 8 * (size_t)ldo) = (u32)h0 | ((u32)h1 << 16);
            }
        }
    }
}

// ---------------- prepass: split all 4 weights in ONE launch -------------------
__global__ void __launch_bounds__(256)
wsplit_kernel(const float* __restrict__ Wt, const float* __restrict__ Wp,
              const float* __restrict__ Wg, const float* __restrict__ Wo,
              u16* wth, u16* wtl, u16* wph, u16* wpl,
              u16* wgh, u16* wgl, u16* woh, u16* wol)
{
    int i = blockIdx.x * 256 + threadIdx.x;   // < CI*CC = 2M
    u16 h, l;
    switch (blockIdx.y) {
        case 0: split_bf(Wt[i], h, l); wth[i] = h; wtl[i] = l; break;
        case 1: split_bf(Wp[i], h, l); wph[i] = h; wpl[i] = l; break;
        case 2: split_fp(Wg[i], h, l); wgh[i] = h; wgl[i] = l; break;
        default: split_fp(Wo[i], h, l); woh[i] = h; wol[i] = l; break;
    }
}

// x [b][c][n] -> xT bf16 h/l + fp16 single [b][n][c]
__global__ void __launch_bounds__(256)
xpose_split_kernel(const float* __restrict__ x, u16* __restrict__ bh,
                   u16* __restrict__ bl, u16* __restrict__ fh) {
    __shared__ float t[32][33];
    const int b = blockIdx.z;
    const int n0 = blockIdx.x * 32, c0 = blockIdx.y * 32;
    const int tx = threadIdx.x & 31, ty = threadIdx.x >> 5;
    const float* xp = x + ((size_t)b * CC + c0) * NSP + n0;
#pragma unroll
    for (int i = 0; i < 4; ++i)
        t[ty + i * 8][tx] = xp[(size_t)(ty + i * 8) * NSP + tx];
    __syncthreads();
    const size_t ob = ((size_t)b * NSP + n0) * CC + c0;
#pragma unroll
    for (int i = 0; i < 4; ++i) {
        float v = t[tx][ty + i * 8];
        size_t idx = ob + (size_t)(ty + i * 8) * CC + tx;
        u16 h, l;
        split_bf(v, h, l);
        bh[idx] = h; bl[idx] = l;
        fh[idx] = __half_as_ushort(__float2half_rn(v));
    }
}

// ---------------- softmax over rows of 512 -> fp16 hi/lo -----------------------
__global__ void __launch_bounds__(256)
softmax_split_kernel(const float* __restrict__ f, u16* __restrict__ ah,
                     u16* __restrict__ al) {
    const size_t off = (size_t)blockIdx.x * NSP;
    const float* p = f + off;
    const int t = threadIdx.x;
    float v0 = p[t];
    float v1 = p[t + 256];

    __shared__ float red[8];
    float m = fmaxf(v0, v1);
#pragma unroll
    for (int o = 16; o; o >>= 1) m = fmaxf(m, __shfl_xor_sync(0xffffffffu, m, o));
    if ((t & 31) == 0) red[t >> 5] = m;
    __syncthreads();
    float M = red[0];
#pragma unroll
    for (int i = 1; i < 8; ++i) M = fmaxf(M, red[i]);
    __syncthreads();

    float e0 = expf(v0 - M);
    float e1 = expf(v1 - M);
    float s = e0 + e1;
#pragma unroll
    for (int o = 16; o; o >>= 1) s += __shfl_xor_sync(0xffffffffu, s, o);
    if ((t & 31) == 0) red[t >> 5] = s;
    __syncthreads();
    float S = 0.f;
#pragma unroll
    for (int i = 0; i < 8; ++i) S += red[i];

    const float inv = 1.f / S;
    u16 h, l;
    split_fp(e0 * inv, h, l);  ah[off + t] = h;        al[off + t] = l;
    split_fp(e1 * inv, h, l);  ah[off + t + 256] = h;  al[off + t + 256] = l;
}

// ---------------- BN stats & apply ----------------------------------------------
__global__ void __launch_bounds__(256)
bn_stats_kernel(const float* __restrict__ wy, float* __restrict__ mean,
                float* __restrict__ rstd) {
    const int o = blockIdx.x;
    const int t = threadIdx.x;
    double ds = 0.0, dss = 0.0;
    for (int i = t; i < BB * NSP; i += 256) {
        const int b = i >> 9;
        const int n = i & (NSP - 1);
        const float v = wy[((size_t)b * CC + o) * NSP + n];
        ds  += (double)v;
        dss += (double)v * (double)v;
    }
    __shared__ double r1[256];
    __shared__ double r2[256];
    r1[t] = ds; r2[t] = dss;
    __syncthreads();
    for (int st = 128; st; st >>= 1) {
        if (t < st) { r1[t] += r1[t + st]; r2[t] += r2[t + st]; }
        __syncthreads();
    }
    if (t == 0) {
        const double cnt = (double)(BB * NSP);
        const double mu  = r1[0] / cnt;
        const double var = r2[0] / cnt - mu * mu;
        mean[o] = (float)mu;
        rstd[o] = (float)rsqrt(var + 1e-5);
    }
}

__global__ void __launch_bounds__(256)
bn_apply_kernel(float* __restrict__ out, const float* __restrict__ x,
                const float* __restrict__ mean, const float* __restrict__ rstd,
                const float* __restrict__ gamma, const float* __restrict__ beta) {
    const long i4 = (long)blockIdx.x * blockDim.x + threadIdx.x;
    const long e = i4 * 4;
    const int c = (int)((e >> 9) & (CC - 1));
    const float mu = mean[c];
    const float rs = rstd[c];
    const float ga = gamma[c];
    const float be = beta[c];
    float4 w  = *reinterpret_cast<const float4*>(&out[e]);
    float4 xv = *reinterpret_cast<const float4*>(&x[e]);
    w.x = (w.x - mu) * rs * ga + be + xv.x;
    w.y = (w.y - mu) * rs * ga + be + xv.y;
    w.z = (w.z - mu) * rs * ga + be + xv.z;
    w.w = (w.w - mu) * rs * ga + be + xv.w;
    *reinterpret_cast<float4*>(&out[e]) = w;
}

// -------------------------------------------------------------------------------
extern "C" void kernel_launch(void* const* d_in, const int* in_sizes, int n_in,
                              void* d_out, int out_size)
{
    const float* x     = (const float*)d_in[0];
    const float* Wg    = (const float*)d_in[1];
    const float* bg    = (const float*)d_in[2];
    const float* Wt    = (const float*)d_in[3];
    const float* bt    = (const float*)d_in[4];
    const float* Wp    = (const float*)d_in[5];
    const float* bp    = (const float*)d_in[6];
    const float* Wo    = (const float*)d_in[7];
    const float* bo    = (const float*)d_in[8];
    const float* gamma = (const float*)d_in[9];
    const float* beta  = (const float*)d_in[10];
    float* out = (float*)d_out;

    u16 *xTbh, *xTbl, *xTf, *Wth, *Wtl, *Wph, *Wpl, *Wgh, *Wgl, *Woh, *Wol;
    u16 *thh, *thl, *phh, *phl, *gf, *ath, *atl, *yT;
    float *f, *mean, *rstd;
    cudaGetSymbolAddress((void**)&xTbh, g_xTbh); cudaGetSymbolAddress((void**)&xTbl, g_xTbl);
    cudaGetSymbolAddress((void**)&xTf,  g_xTf);
    cudaGetSymbolAddress((void**)&Wth, g_Wth); cudaGetSymbolAddress((void**)&Wtl, g_Wtl);
    cudaGetSymbolAddress((void**)&Wph, g_Wph); cudaGetSymbolAddress((void**)&Wpl, g_Wpl);
    cudaGetSymbolAddress((void**)&Wgh, g_Wgh); cudaGetSymbolAddress((void**)&Wgl, g_Wgl);
    cudaGetSymbolAddress((void**)&Woh, g_Woh); cudaGetSymbolAddress((void**)&Wol, g_Wol);
    cudaGetSymbolAddress((void**)&thh, g_thh); cudaGetSymbolAddress((void**)&thl, g_thl);
    cudaGetSymbolAddress((void**)&phh, g_phh); cudaGetSymbolAddress((void**)&phl, g_phl);
    cudaGetSymbolAddress((void**)&gf,  g_gf);
    cudaGetSymbolAddress((void**)&ath, g_ath); cudaGetSymbolAddress((void**)&atl, g_atl);
    cudaGetSymbolAddress((void**)&yT,  g_yT);
    cudaGetSymbolAddress((void**)&f,   g_f);
    cudaGetSymbolAddress((void**)&mean, g_mean); cudaGetSymbolAddress((void**)&rstd, g_rstd);

    const int SM3 = 3 * 49152;  // 147456
    const int SM2 = 3 * 32768;  // 98304
    cudaFuncSetAttribute((const void*)hgemm<0,3,1,2>, cudaFuncAttributeMaxDynamicSharedMemorySize, SM3);
    cudaFuncSetAttribute((const void*)hgemm<0,3,0,0>, cudaFuncAttributeMaxDynamicSharedMemorySize, SM3);
    cudaFuncSetAttribute((const void*)hgemm<1,2,2,1>, cudaFuncAttributeMaxDynamicSharedMemorySize, SM2);
    cudaFuncSetAttribute((const void*)hgemm<1,2,2,0>, cudaFuncAttributeMaxDynamicSharedMemorySize, SM2);
    cudaFuncSetAttribute((const void*)hgemm<1,2,0,1>, cudaFuncAttributeMaxDynamicSharedMemorySize, SM2);

    const long bs_xT = (long)NSP * CC;
    const long bs_pT = (long)NSP * CI;
    const long bs_g  = (long)CI * NSP;
    const long bs_f  = (long)NSP * NSP;
    const long bs_o  = (long)CC * NSP;

    // 0) weights split (one launch)
    wsplit_kernel<<<dim3((CI * CC) / 256, 4), 256>>>(
        Wt, Wp, Wg, Wo, Wth, Wtl, Wph, Wpl, Wgh, Wgl, Woh, Wol);
    // 1) x -> xT (bf16 h/l + fp16)
    xpose_split_kernel<<<dim3(NSP / 32, CC / 32, BB), 256>>>(x, xTbh, xTbl, xTf);

    // 2) g[ci][m] = Wg . xT + bg   (fp16 2-MMA, row bias, fp16 out)
    hgemm<1,2,2,1><<<dim3(NSP/256, CI/128, BB), 256, SM2>>>(
        Wgh, Wgl, xTf, nullptr, gf, nullptr, bg, CC, NSP, 0L, bs_xT, bs_g);
    // 3) thT[n][ci] = xT . Wt + bt  (bf16 3-MMA, col bias, bf16 h/l out)
    hgemm<0,3,1,2><<<dim3(CI/256, NSP/128, BB), 256, SM3>>>(
        xTbh, xTbl, Wth, Wtl, thh, thl, bt, CC, CI, bs_xT, 0L, bs_pT);
    // 4) phT
    hgemm<0,3,1,2><<<dim3(CI/256, NSP/128, BB), 256, SM3>>>(
        xTbh, xTbl, Wph, Wpl, phh, phl, bp, CC, CI, bs_xT, 0L, bs_pT);
    // 5) f[n][m] = thT . phT        (bf16 3-MMA, fp32 out)  <- ncu -s 5 samples this
    hgemm<0,3,0,0><<<dim3(NSP/256, NSP/128, BB), 256, SM3>>>(
        thh, thl, phh, phl, f, nullptr, nullptr, CI, NSP, bs_pT, bs_pT, bs_f);
    // 6) softmax -> attn fp16 h/l
    softmax_split_kernel<<<BB * NSP, 256>>>(f, ath, atl);
    // 7) yT[n][ci] = attn . g       (fp16 2-MMA, fp16 out)
    hgemm<1,2,2,0><<<dim3(CI/256, NSP/128, BB), 256, SM2>>>(
        ath, atl, gf, nullptr, yT, nullptr, nullptr, NSP, CI, bs_f, bs_g, bs_pT);
    // 8) out[o][n] = Wo . yT + bo   (fp16 2-MMA, fp32 -> d_out)
    hgemm<1,2,0,1><<<dim3(NSP/256, CC/128, BB), 256, SM2>>>(
        Woh, Wol, yT, nullptr, out, nullptr, bo, CI, NSP, 0L, bs_pT, bs_o);

    // 9) BN stats + apply + residual
    bn_stats_kernel<<<CC, 256>>>(out, mean, rstd);
    {
        const long total4 = (long)BB * CC * NSP / 4;
        bn_apply_kernel<<<(unsigned)(total4 / 256), 256>>>(out, x, mean, rstd, gamma, beta);
    }
}